// round 1
// baseline (speedup 1.0000x reference)
#include <cuda_runtime.h>

#define SEQ   2048          // B*A
#define NT    121           // tokens
#define HDIM  128           // hidden
#define FIND  12            // feature in
#define NHEAD 4
#define HDH   32            // head dim
#define OUTD  256
#define MTOK  (SEQ*NT)      // 247808
#define KBIG  (NT*HDIM)     // 15488
#define EPSV  1e-5f

// ---------------- scratch (device globals; no allocation allowed) ----------
__device__ float g_x  [(size_t)MTOK * HDIM];
__device__ float g_qkv[(size_t)MTOK * 384];
__device__ float g_att[(size_t)MTOK * HDIM];
__device__ float g_tmp[(size_t)MTOK * HDIM];
__device__ float g_h  [(size_t)MTOK * HDIM];
__device__ float g_y  [(size_t)SEQ * OUTD];

// ---------------- embed: forest @ w_in^T + b_in + tree PE, then permute ----
__global__ void embed_kernel(const float* __restrict__ forest,
                             const int*   __restrict__ perm,
                             const float* __restrict__ w_in,
                             const float* __restrict__ b_in,
                             float* __restrict__ out)
{
    int tok = blockIdx.x;              // 0..MTOK-1 (output token position)
    int s = tok / NT, i = tok - s * NT;
    int node = perm[i];
    int h = threadIdx.x;               // 128
    __shared__ float fs[FIND];
    const float* f = forest + ((size_t)s * NT + node) * FIND;
    if (h < FIND) fs[h] = f[h];
    __syncthreads();
    float acc = b_in[h];
#pragma unroll
    for (int k = 0; k < FIND; k++) acc += fs[k] * w_in[h * FIND + k];
    // tree positional encoding: walk to root, bit (depth-1)*3 + branch
    if (h < 12) {
        int mask = 0, cur = node;
        while (cur > 0) {
            int d = (cur >= 40) ? 4 : (cur >= 13) ? 3 : (cur >= 4) ? 2 : 1;
            int br = (cur - 1) % 3;
            mask |= 1 << ((d - 1) * 3 + br);
            cur = (cur - 1) / 3;
        }
        acc += (float)((mask >> h) & 1);
    }
    out[(size_t)tok * HDIM + h] = acc;
}

// ---------------- generic SGEMM: C[M,Nc] = X[M,K] @ W[Nc,K]^T + bias -------
// 64x64 tile, BK=16, 256 threads, 4x4 microtile. M%64==0, Nc%64==0, K%16==0.
__global__ void gemm_bias_kernel(const float* __restrict__ X,
                                 const float* __restrict__ W,
                                 const float* __restrict__ bias,
                                 float* __restrict__ C,
                                 int M, int Nc, int K, int relu)
{
    __shared__ float Xs[16][68];
    __shared__ float Ws[16][68];
    int tid = threadIdx.x;
    int tx = tid & 15, ty = tid >> 4;
    int row0 = blockIdx.y * 64, col0 = blockIdx.x * 64;
    int lr = tid >> 2;
    int lc = (tid & 3) << 2;
    float acc[4][4] = {};
    const float* Xp = X + (size_t)(row0 + lr) * K + lc;
    const float* Wp = W + (size_t)(col0 + lr) * K + lc;
    for (int k0 = 0; k0 < K; k0 += 16) {
        float4 xv = *(const float4*)(Xp + k0);
        float4 wv = *(const float4*)(Wp + k0);
        Xs[lc + 0][lr] = xv.x; Xs[lc + 1][lr] = xv.y;
        Xs[lc + 2][lr] = xv.z; Xs[lc + 3][lr] = xv.w;
        Ws[lc + 0][lr] = wv.x; Ws[lc + 1][lr] = wv.y;
        Ws[lc + 2][lr] = wv.z; Ws[lc + 3][lr] = wv.w;
        __syncthreads();
#pragma unroll
        for (int kk = 0; kk < 16; kk++) {
            float4 a = *(const float4*)&Xs[kk][ty * 4];
            float4 b = *(const float4*)&Ws[kk][tx * 4];
            float av[4] = {a.x, a.y, a.z, a.w};
            float bv[4] = {b.x, b.y, b.z, b.w};
#pragma unroll
            for (int i = 0; i < 4; i++)
#pragma unroll
                for (int j = 0; j < 4; j++) acc[i][j] += av[i] * bv[j];
        }
        __syncthreads();
    }
#pragma unroll
    for (int i = 0; i < 4; i++) {
        int r = row0 + ty * 4 + i;
#pragma unroll
        for (int j = 0; j < 4; j++) {
            int c = col0 + tx * 4 + j;
            float v = acc[i][j] + bias[c];
            if (relu) v = fmaxf(v, 0.f);
            C[(size_t)r * Nc + c] = v;
        }
    }
}

// ---------------- split-K SGEMM for the deep output projection -------------
__global__ void gemm_splitk_kernel(const float* __restrict__ X,
                                   const float* __restrict__ W,
                                   float* __restrict__ C,
                                   int M, int Nc, int K, int kchunk)
{
    __shared__ float Xs[16][68];
    __shared__ float Ws[16][68];
    int tid = threadIdx.x;
    int tx = tid & 15, ty = tid >> 4;
    int row0 = blockIdx.y * 64, col0 = blockIdx.x * 64;
    int kstart = blockIdx.z * kchunk;
    int lr = tid >> 2;
    int lc = (tid & 3) << 2;
    float acc[4][4] = {};
    const float* Xp = X + (size_t)(row0 + lr) * K + kstart + lc;
    const float* Wp = W + (size_t)(col0 + lr) * K + kstart + lc;
    for (int k0 = 0; k0 < kchunk; k0 += 16) {
        float4 xv = *(const float4*)(Xp + k0);
        float4 wv = *(const float4*)(Wp + k0);
        Xs[lc + 0][lr] = xv.x; Xs[lc + 1][lr] = xv.y;
        Xs[lc + 2][lr] = xv.z; Xs[lc + 3][lr] = xv.w;
        Ws[lc + 0][lr] = wv.x; Ws[lc + 1][lr] = wv.y;
        Ws[lc + 2][lr] = wv.z; Ws[lc + 3][lr] = wv.w;
        __syncthreads();
#pragma unroll
        for (int kk = 0; kk < 16; kk++) {
            float4 a = *(const float4*)&Xs[kk][ty * 4];
            float4 b = *(const float4*)&Ws[kk][tx * 4];
            float av[4] = {a.x, a.y, a.z, a.w};
            float bv[4] = {b.x, b.y, b.z, b.w};
#pragma unroll
            for (int i = 0; i < 4; i++)
#pragma unroll
                for (int j = 0; j < 4; j++) acc[i][j] += av[i] * bv[j];
        }
        __syncthreads();
    }
#pragma unroll
    for (int i = 0; i < 4; i++) {
        int r = row0 + ty * 4 + i;
#pragma unroll
        for (int j = 0; j < 4; j++) {
            int c = col0 + tx * 4 + j;
            atomicAdd(&C[(size_t)r * Nc + c], acc[i][j]);
        }
    }
}

__global__ void init_y_kernel(const float* __restrict__ b_out, float* __restrict__ y)
{
    int i = blockIdx.x * blockDim.x + threadIdx.x;
    y[i] = b_out[i & (OUTD - 1)];
}

// ---------------- fused attention: one block per (seq, head) ---------------
__global__ void attn_kernel(const float* __restrict__ qkv, float* __restrict__ out)
{
    int s  = blockIdx.x >> 2;
    int hh = blockIdx.x & 3;
    int t = threadIdx.x, warp = t >> 5, lane = t & 31;
    __shared__ float qs[NT][33];
    __shared__ float ks[NT][33];
    __shared__ float ps[4][NT];
    const float* base = qkv + (size_t)s * NT * 384;
    for (int idx = t; idx < NT * HDH; idx += 128) {
        int n = idx >> 5, d = idx & 31;
        qs[n][d] = base[(size_t)n * 384 + hh * HDH + d];
        ks[n][d] = base[(size_t)n * 384 + 128 + hh * HDH + d];
    }
    __syncthreads();
    const float scale = 0.17677669529663687f;  // 1/sqrt(32)
    const float* vb = base + 256 + hh * HDH;
    for (int q = warp; q < NT; q += 4) {
        float lg[4];
        float mx = -1e30f;
#pragma unroll
        for (int j = 0; j < 4; j++) {
            int key = lane + j * 32;
            float a = -1e30f;
            if (key < NT) {
                float acc = 0.f;
#pragma unroll
                for (int d = 0; d < HDH; d++) acc += qs[q][d] * ks[key][d];
                a = acc * scale;
            }
            lg[j] = a;
            mx = fmaxf(mx, a);
        }
#pragma unroll
        for (int o = 16; o; o >>= 1) mx = fmaxf(mx, __shfl_xor_sync(0xffffffffu, mx, o));
        float sum = 0.f;
#pragma unroll
        for (int j = 0; j < 4; j++) {
            int key = lane + j * 32;
            float e = (key < NT) ? __expf(lg[j] - mx) : 0.f;
            lg[j] = e;
            sum += e;
        }
#pragma unroll
        for (int o = 16; o; o >>= 1) sum += __shfl_xor_sync(0xffffffffu, sum, o);
        float inv = 1.f / sum;
#pragma unroll
        for (int j = 0; j < 4; j++) {
            int key = lane + j * 32;
            if (key < NT) ps[warp][key] = lg[j] * inv;
        }
        __syncwarp();
        float o0 = 0.f;
        for (int kx = 0; kx < NT; kx++) o0 += ps[warp][kx] * vb[(size_t)kx * 384 + lane];
        out[((size_t)s * NT + q) * HDIM + hh * HDH + lane] = o0;
        __syncwarp();
    }
}

// ---------------- add-residual + LayerNorm (one row per block) -------------
__global__ void addln_kernel(const float* __restrict__ xin,
                             const float* __restrict__ res,
                             const float* __restrict__ g,
                             const float* __restrict__ b,
                             float* __restrict__ out, int C)
{
    int row = blockIdx.x, t = threadIdx.x;   // blockDim.x == C
    size_t base = (size_t)row * C;
    float v = xin[base + t];
    if (res) v += res[base + t];
    __shared__ float red[9];
    int lane = t & 31, warp = t >> 5, nw = blockDim.x >> 5;
    float s = v;
#pragma unroll
    for (int o = 16; o; o >>= 1) s += __shfl_xor_sync(0xffffffffu, s, o);
    if (lane == 0) red[warp] = s;
    __syncthreads();
    if (t == 0) { float tot = 0; for (int i = 0; i < nw; i++) tot += red[i]; red[8] = tot; }
    __syncthreads();
    float mean = red[8] / (float)C;
    float d = v - mean;
    float s2 = d * d;
#pragma unroll
    for (int o = 16; o; o >>= 1) s2 += __shfl_xor_sync(0xffffffffu, s2, o);
    __syncthreads();
    if (lane == 0) red[warp] = s2;
    __syncthreads();
    if (t == 0) { float tot = 0; for (int i = 0; i < nw; i++) tot += red[i]; red[8] = tot; }
    __syncthreads();
    float var = red[8] / (float)C;
    out[base + t] = d * rsqrtf(var + EPSV) * g[t] + b[t];
}

// ---------------- launch ---------------------------------------------------
extern "C" void kernel_launch(void* const* d_in, const int* in_sizes, int n_in,
                              void* d_out, int out_size)
{
    const float* forest = (const float*)d_in[0];
    // d_in[1] = adjacency (deterministic ternary tree; PE computed in closed form)
    const int*   perm   = (const int*)  d_in[2];
    const float* w_in   = (const float*)d_in[3];
    const float* b_in   = (const float*)d_in[4];
    const float* qkv_w  = (const float*)d_in[5];
    const float* qkv_b  = (const float*)d_in[6];
    const float* proj_w = (const float*)d_in[7];
    const float* proj_b = (const float*)d_in[8];
    const float* ff1_w  = (const float*)d_in[9];
    const float* ff1_b  = (const float*)d_in[10];
    const float* ff2_w  = (const float*)d_in[11];
    const float* ff2_b  = (const float*)d_in[12];
    const float* ln1_g  = (const float*)d_in[13];
    const float* ln1_b  = (const float*)d_in[14];
    const float* ln2_g  = (const float*)d_in[15];
    const float* ln2_b  = (const float*)d_in[16];
    const float* w_out  = (const float*)d_in[17];
    const float* b_out  = (const float*)d_in[18];
    const float* lnf_g  = (const float*)d_in[19];
    const float* lnf_b  = (const float*)d_in[20];

    float *xb, *qb, *ab, *tb, *hb, *yb;
    cudaGetSymbolAddress((void**)&xb, g_x);
    cudaGetSymbolAddress((void**)&qb, g_qkv);
    cudaGetSymbolAddress((void**)&ab, g_att);
    cudaGetSymbolAddress((void**)&tb, g_tmp);
    cudaGetSymbolAddress((void**)&hb, g_h);
    cudaGetSymbolAddress((void**)&yb, g_y);

    embed_kernel<<<MTOK, 128>>>(forest, perm, w_in, b_in, xb);

    for (int l = 0; l < 2; l++) {
        gemm_bias_kernel<<<dim3(384 / 64, MTOK / 64), 256>>>(
            xb, qkv_w + (size_t)l * 384 * 128, qkv_b + l * 384, qb, MTOK, 384, 128, 0);
        attn_kernel<<<SEQ * NHEAD, 128>>>(qb, ab);
        gemm_bias_kernel<<<dim3(2, MTOK / 64), 256>>>(
            ab, proj_w + (size_t)l * 128 * 128, proj_b + l * 128, tb, MTOK, 128, 128, 0);
        addln_kernel<<<MTOK, 128>>>(xb, tb, ln1_g + l * 128, ln1_b + l * 128, xb, 128);
        gemm_bias_kernel<<<dim3(2, MTOK / 64), 256>>>(
            xb, ff1_w + (size_t)l * 128 * 128, ff1_b + l * 128, hb, MTOK, 128, 128, 1);
        gemm_bias_kernel<<<dim3(2, MTOK / 64), 256>>>(
            hb, ff2_w + (size_t)l * 128 * 128, ff2_b + l * 128, tb, MTOK, 128, 128, 0);
        addln_kernel<<<MTOK, 128>>>(xb, tb, ln2_g + l * 128, ln2_b + l * 128, xb, 128);
    }

    init_y_kernel<<<(SEQ * OUTD) / 256, 256>>>(b_out, yb);
    gemm_splitk_kernel<<<dim3(OUTD / 64, SEQ / 64, 8), 256>>>(
        xb, w_out, yb, SEQ, OUTD, KBIG, KBIG / 8);
    addln_kernel<<<SEQ, 256>>>(yb, nullptr, lnf_g, lnf_b, (float*)d_out, 256);
}